// round 2
// baseline (speedup 1.0000x reference)
#include <cuda_runtime.h>
#include <math.h>

#define B_  32
#define L_  32768
#define PS_ 32
#define D_  256
#define T_  1024
#define M_  (B_ * T_)          // 32768 total patch rows

#define NEG_INF __int_as_float(0xff800000)

// ---------------- scratch (module-static device memory; no runtime alloc) ---
__device__ float  g_xn [B_ * L_];          //  4 MB  normalized x (== patches)
__device__ float  g_h  [M_ * D_];          // 32 MB  patch embeddings
__device__ float  g_qkv[M_ * 3 * D_];      // 96 MB  q|k|v
__device__ float  g_att[M_ * D_];          // 32 MB  attention output
__device__ float  g_out[M_ * D_];          // 32 MB  out-proj
__device__ double g_loss;

// ============================================================================
// 1) Instance norm over full series, ddof=1, std + 1e-5 (torch semantics)
// ============================================================================
__global__ void norm_kernel(const float* __restrict__ x) {
    const int b   = blockIdx.x;
    const int tid = threadIdx.x;            // 1024 threads
    const float* xr = x + (size_t)b * L_;

    float s = 0.f, ss = 0.f;
    for (int i = tid; i < L_; i += 1024) {
        float v = xr[i];
        s += v; ss += v * v;
    }
    __shared__ float sh_s[1024], sh_ss[1024];
    sh_s[tid] = s; sh_ss[tid] = ss;
    __syncthreads();
    for (int o = 512; o > 0; o >>= 1) {
        if (tid < o) { sh_s[tid] += sh_s[tid + o]; sh_ss[tid] += sh_ss[tid + o]; }
        __syncthreads();
    }
    const float sum  = sh_s[0];
    const float mean = sum / (float)L_;
    const float var  = (sh_ss[0] - sum * mean) / (float)(L_ - 1);   // ddof=1
    const float inv  = 1.0f / (sqrtf(var) + 1e-5f);

    float* o = g_xn + (size_t)b * L_;
    for (int i = tid; i < L_; i += 1024) o[i] = (xr[i] - mean) * inv;

    if (b == 0 && tid == 0) g_loss = 0.0;   // stream-ordered before head kernel
}

// ============================================================================
// 2) Tiled SGEMM: C[M][N] = A[M][K] @ W[K][N] + bias
//    BM=BN=128, BK=16, 256 threads, 8x8 register tiles (2x2 quadrants of 4x4).
//    Per k-step per thread: 4 LDS.128 + 64 FFMA -> FFMA-bound (2x LDS headroom).
//    Requires M%128==0, N%128==0, K%16==0 (holds for all three uses).
// ============================================================================
__global__ void __launch_bounds__(256) gemm_bias(
    const float* __restrict__ A, const float* __restrict__ W,
    const float* __restrict__ bias, float* __restrict__ C,
    int M, int N, int K)
{
    __shared__ float Ast[16][132];   // transposed: Ast[k][m], padded (2-way store conflict only)
    __shared__ float Bs [16][128];

    const int tid = threadIdx.x;
    const int tx  = tid & 15, ty = tid >> 4;          // 16x16 thread grid
    const int m0  = blockIdx.y * 128, n0 = blockIdx.x * 128;

    // A-tile: 128x16 = 512 float4, 2 per thread
    const int a_row0 = tid >> 2,          a_c4 = tid & 3;           // idx = tid
    const int a_row1 = (tid + 256) >> 2;                            // idx = tid+256, same c4
    // B-tile: 16x128 = 512 float4, 2 per thread
    const int b_row0 = tid >> 5,          b_c4 = tid & 31;
    const int b_row1 = (tid + 256) >> 5;

    float acc[8][8];
    #pragma unroll
    for (int i = 0; i < 8; i++)
        #pragma unroll
        for (int j = 0; j < 8; j++) acc[i][j] = 0.f;

    for (int kk = 0; kk < K; kk += 16) {
        float4 a0 = *(const float4*)(A + (size_t)(m0 + a_row0) * K + kk + a_c4 * 4);
        float4 a1 = *(const float4*)(A + (size_t)(m0 + a_row1) * K + kk + a_c4 * 4);
        float4 w0 = *(const float4*)(W + (size_t)(kk + b_row0) * N + n0 + b_c4 * 4);
        float4 w1 = *(const float4*)(W + (size_t)(kk + b_row1) * N + n0 + b_c4 * 4);

        Ast[a_c4 * 4 + 0][a_row0] = a0.x;
        Ast[a_c4 * 4 + 1][a_row0] = a0.y;
        Ast[a_c4 * 4 + 2][a_row0] = a0.z;
        Ast[a_c4 * 4 + 3][a_row0] = a0.w;
        Ast[a_c4 * 4 + 0][a_row1] = a1.x;
        Ast[a_c4 * 4 + 1][a_row1] = a1.y;
        Ast[a_c4 * 4 + 2][a_row1] = a1.z;
        Ast[a_c4 * 4 + 3][a_row1] = a1.w;
        *(float4*)&Bs[b_row0][b_c4 * 4] = w0;
        *(float4*)&Bs[b_row1][b_c4 * 4] = w1;
        __syncthreads();

        #pragma unroll
        for (int k = 0; k < 16; k++) {
            float4 va0 = *(const float4*)&Ast[k][ty * 4];
            float4 va1 = *(const float4*)&Ast[k][64 + ty * 4];
            float4 vb0 = *(const float4*)&Bs [k][tx * 4];
            float4 vb1 = *(const float4*)&Bs [k][64 + tx * 4];
            float af[8] = {va0.x, va0.y, va0.z, va0.w, va1.x, va1.y, va1.z, va1.w};
            float bf[8] = {vb0.x, vb0.y, vb0.z, vb0.w, vb1.x, vb1.y, vb1.z, vb1.w};
            #pragma unroll
            for (int i = 0; i < 8; i++)
                #pragma unroll
                for (int j = 0; j < 8; j++)
                    acc[i][j] = fmaf(af[i], bf[j], acc[i][j]);
        }
        __syncthreads();
    }

    const float4 bia0 = *(const float4*)(bias + n0 + tx * 4);
    const float4 bia1 = *(const float4*)(bias + n0 + 64 + tx * 4);
    #pragma unroll
    for (int i = 0; i < 8; i++) {
        const int row = m0 + ((i < 4) ? (ty * 4 + i) : (64 + ty * 4 + i - 4));
        float* cp = C + (size_t)row * N + n0;
        float4 o0, o1;
        o0.x = acc[i][0] + bia0.x; o0.y = acc[i][1] + bia0.y;
        o0.z = acc[i][2] + bia0.z; o0.w = acc[i][3] + bia0.w;
        o1.x = acc[i][4] + bia1.x; o1.y = acc[i][5] + bia1.y;
        o1.z = acc[i][6] + bia1.z; o1.w = acc[i][7] + bia1.w;
        *(float4*)(cp + tx * 4)      = o0;
        *(float4*)(cp + 64 + tx * 4) = o1;
    }
}

// ============================================================================
// 3) Causal flash attention, BQ=BK=64, D=256, fp32.
//    Grid (16, 32): x = q-block (reversed for heavy-first), y = batch.
//    smem: Q^T[256][64], K^T[256][64], V[64][256], S[64][65], stats.
// ============================================================================
#define ATT_SMEM_FLOATS (3 * 16384 + 64 * 65 + 192)

__global__ void __launch_bounds__(256, 1) attn_kernel() {
    extern __shared__ float sm[];
    float* Qt      = sm;                    // [256][64] (scaled by 1/sqrt(D))
    float* Kt      = sm + 16384;            // [256][64]
    float* Vs      = sm + 32768;            // [64][256]
    float* S       = sm + 49152;            // [64][65]
    float* m_row   = sm + 49152 + 64 * 65;
    float* l_row   = m_row + 64;
    float* alpha_s = l_row + 64;

    const int tid = threadIdx.x;
    const int b   = blockIdx.y;
    const int qb  = 15 - (int)blockIdx.x;   // heavy q-blocks first
    const int t0  = qb * 64;
    const int ty  = tid >> 4, tx = tid & 15;

    // Load Q^T, pre-scaled by 1/16
    {
        const float* qbase = g_qkv + (size_t)(b * T_ + t0) * 768;
        for (int fi = tid; fi < 64 * 64; fi += 256) {
            int r = fi >> 6, dv = fi & 63;
            float4 v = *(const float4*)(qbase + (size_t)r * 768 + dv * 4);
            Qt[(dv * 4 + 0) * 64 + r] = v.x * 0.0625f;
            Qt[(dv * 4 + 1) * 64 + r] = v.y * 0.0625f;
            Qt[(dv * 4 + 2) * 64 + r] = v.z * 0.0625f;
            Qt[(dv * 4 + 3) * 64 + r] = v.w * 0.0625f;
        }
    }
    if (tid < 64) { m_row[tid] = NEG_INF; l_row[tid] = 0.f; }

    float4 o4[4][4];
    #pragma unroll
    for (int i = 0; i < 4; i++)
        #pragma unroll
        for (int j = 0; j < 4; j++) o4[i][j] = make_float4(0.f, 0.f, 0.f, 0.f);

    for (int kb = 0; kb <= qb; kb++) {
        __syncthreads();   // protects Kt/Vs reuse, covers Q-load + stats init on iter 0

        // ---- load K^T and V for this k-block ----
        {
            const float* kvb = g_qkv + (size_t)(b * T_ + kb * 64) * 768;
            for (int fi = tid; fi < 64 * 64; fi += 256) {
                int r = fi >> 6, dv = fi & 63;
                float4 kv = *(const float4*)(kvb + (size_t)r * 768 + 256 + dv * 4);
                Kt[(dv * 4 + 0) * 64 + r] = kv.x;
                Kt[(dv * 4 + 1) * 64 + r] = kv.y;
                Kt[(dv * 4 + 2) * 64 + r] = kv.z;
                Kt[(dv * 4 + 3) * 64 + r] = kv.w;
                float4 vv = *(const float4*)(kvb + (size_t)r * 768 + 512 + dv * 4);
                *(float4*)(Vs + r * 256 + dv * 4) = vv;
            }
        }
        __syncthreads();

        // ---- Phase A: S = (Q*scale) @ K^T, 4x4 register tile per thread ----
        float acc[4][4];
        #pragma unroll
        for (int i = 0; i < 4; i++)
            #pragma unroll
            for (int j = 0; j < 4; j++) acc[i][j] = 0.f;

        #pragma unroll 4
        for (int d = 0; d < 256; d++) {
            float4 qa = *(const float4*)(Qt + d * 64 + ty * 4);
            float4 ka = *(const float4*)(Kt + d * 64 + tx * 4);
            float qv[4] = {qa.x, qa.y, qa.z, qa.w};
            float kv[4] = {ka.x, ka.y, ka.z, ka.w};
            #pragma unroll
            for (int i = 0; i < 4; i++)
                #pragma unroll
                for (int j = 0; j < 4; j++)
                    acc[i][j] = fmaf(qv[i], kv[j], acc[i][j]);
        }
        const bool diag = (kb == qb);
        #pragma unroll
        for (int i = 0; i < 4; i++)
            #pragma unroll
            for (int j = 0; j < 4; j++) {
                float v = acc[i][j];
                if (diag && (tx * 4 + j > ty * 4 + i)) v = NEG_INF;
                S[(ty * 4 + i) * 65 + tx * 4 + j] = v;
            }
        __syncthreads();

        // ---- Phase B: online softmax (4 lanes per row) ----
        {
            const int row = tid >> 2, qq = tid & 3;
            float sv[16];
            float mloc = NEG_INF;
            #pragma unroll
            for (int j = 0; j < 16; j++) {
                sv[j] = S[row * 65 + qq * 16 + j];
                mloc  = fmaxf(mloc, sv[j]);
            }
            mloc = fmaxf(mloc, __shfl_xor_sync(0xffffffffu, mloc, 1));
            mloc = fmaxf(mloc, __shfl_xor_sync(0xffffffffu, mloc, 2));
            const float m_prev = m_row[row];
            const float m_new  = fmaxf(m_prev, mloc);
            const float al     = __expf(m_prev - m_new);   // exp(-inf)=0 on iter 0
            float lloc = 0.f;
            #pragma unroll
            for (int j = 0; j < 16; j++) {
                float p = __expf(sv[j] - m_new);           // masked -inf -> 0
                S[row * 65 + qq * 16 + j] = p;
                lloc += p;
            }
            lloc += __shfl_xor_sync(0xffffffffu, lloc, 1);
            lloc += __shfl_xor_sync(0xffffffffu, lloc, 2);
            if (qq == 0) {
                l_row[row]   = l_row[row] * al + lloc;
                m_row[row]   = m_new;
                alpha_s[row] = al;
            }
        }
        __syncthreads();

        // ---- Phase C: O = O*alpha + P @ V ----
        {
            #pragma unroll
            for (int i = 0; i < 4; i++) {
                float a = alpha_s[ty * 4 + i];
                #pragma unroll
                for (int j = 0; j < 4; j++) {
                    o4[i][j].x *= a; o4[i][j].y *= a;
                    o4[i][j].z *= a; o4[i][j].w *= a;
                }
            }
            #pragma unroll 2
            for (int k = 0; k < 64; k++) {
                float p[4];
                #pragma unroll
                for (int i = 0; i < 4; i++) p[i] = S[(ty * 4 + i) * 65 + k];
                float4 vv[4];
                #pragma unroll
                for (int j = 0; j < 4; j++)
                    vv[j] = *(const float4*)(Vs + k * 256 + tx * 16 + j * 4);
                #pragma unroll
                for (int i = 0; i < 4; i++)
                    #pragma unroll
                    for (int j = 0; j < 4; j++) {
                        o4[i][j].x = fmaf(p[i], vv[j].x, o4[i][j].x);
                        o4[i][j].y = fmaf(p[i], vv[j].y, o4[i][j].y);
                        o4[i][j].z = fmaf(p[i], vv[j].z, o4[i][j].z);
                        o4[i][j].w = fmaf(p[i], vv[j].w, o4[i][j].w);
                    }
            }
        }
    }

    // ---- epilogue: normalize by l, write out (coalesced float4) ----
    #pragma unroll
    for (int i = 0; i < 4; i++) {
        const float inv = 1.0f / l_row[ty * 4 + i];
        float* ob = g_att + (size_t)(b * T_ + t0 + ty * 4 + i) * 256 + tx * 16;
        #pragma unroll
        for (int j = 0; j < 4; j++) {
            float4 v = o4[i][j];
            v.x *= inv; v.y *= inv; v.z *= inv; v.w *= inv;
            *(float4*)(ob + j * 4) = v;
        }
    }
}

// ============================================================================
// 4) Head GEMM (K=256, N=32) fused with shifted-target MSE reduction
// ============================================================================
#define HEAD_SMEM_FLOATS (8192 + 32 * 260 + 256)

__global__ void __launch_bounds__(256) head_loss_kernel(
    const float* __restrict__ Wh, const float* __restrict__ bh)
{
    extern __shared__ float hsm[];
    float* Whs = hsm;                // [256][32]
    float* As  = hsm + 8192;         // [32][260] padded
    float* red = As + 32 * 260;      // [256]

    const int tid = threadIdx.x;
    const int m0  = blockIdx.x * 32;

    for (int fi = tid; fi < 2048; fi += 256)
        *(float4*)(Whs + fi * 4) = *(const float4*)(Wh + fi * 4);
    for (int fi = tid; fi < 2048; fi += 256) {
        int r = fi >> 6, dv = fi & 63;
        *(float4*)(As + r * 260 + dv * 4) =
            *(const float4*)(g_out + (size_t)(m0 + r) * 256 + dv * 4);
    }
    __syncthreads();

    const int rl = tid >> 3, cq = tid & 7;
    float a0 = 0.f, a1 = 0.f, a2 = 0.f, a3 = 0.f;
    #pragma unroll 8
    for (int k = 0; k < 256; k++) {
        float  a = As[rl * 260 + k];
        float4 w = *(const float4*)(Whs + k * 32 + cq * 4);
        a0 = fmaf(a, w.x, a0); a1 = fmaf(a, w.y, a1);
        a2 = fmaf(a, w.z, a2); a3 = fmaf(a, w.w, a3);
    }

    const int m = m0 + rl;
    const int t = m & 1023;
    const int bb = m >> 10;
    float part = 0.f;
    if (t < 1023) {   // pred[:, :-1] vs patches[:, 1:]
        const float* tg = g_xn + (size_t)bb * L_ + (t + 1) * 32 + cq * 4;
        float4 b4 = *(const float4*)(bh + cq * 4);
        float d0 = a0 + b4.x - tg[0];
        float d1 = a1 + b4.y - tg[1];
        float d2 = a2 + b4.z - tg[2];
        float d3 = a3 + b4.w - tg[3];
        part = d0 * d0 + d1 * d1 + d2 * d2 + d3 * d3;
    }
    red[tid] = part;
    __syncthreads();
    for (int o = 128; o > 0; o >>= 1) {
        if (tid < o) red[tid] += red[tid + o];
        __syncthreads();
    }
    if (tid == 0) atomicAdd(&g_loss, (double)red[0]);
}

__global__ void finalize_kernel(float* __restrict__ out) {
    out[0] = (float)(g_loss * (1.0 / (32.0 * 1023.0 * 32.0)));
}

// ============================================================================
// launch
// ============================================================================
extern "C" void kernel_launch(void* const* d_in, const int* in_sizes, int n_in,
                              void* d_out, int out_size) {
    (void)in_sizes; (void)n_in; (void)out_size;
    const float* x      = (const float*)d_in[0];
    const float* W_proj = (const float*)d_in[1];
    const float* b_proj = (const float*)d_in[2];
    const float* W_qkv  = (const float*)d_in[3];
    const float* b_qkv  = (const float*)d_in[4];
    const float* W_out  = (const float*)d_in[5];
    const float* b_out  = (const float*)d_in[6];
    const float* W_head = (const float*)d_in[7];
    const float* b_head = (const float*)d_in[8];
    float* out = (float*)d_out;

    const int ATT_SMEM  = ATT_SMEM_FLOATS  * 4;   // 214016 B
    const int HEAD_SMEM = HEAD_SMEM_FLOATS * 4;   //  67072 B
    cudaFuncSetAttribute(attn_kernel,
        cudaFuncAttributeMaxDynamicSharedMemorySize, ATT_SMEM);
    cudaFuncSetAttribute(head_loss_kernel,
        cudaFuncAttributeMaxDynamicSharedMemorySize, HEAD_SMEM);

    float *p_xn, *p_h, *p_qkv, *p_att, *p_out;
    cudaGetSymbolAddress((void**)&p_xn,  g_xn);
    cudaGetSymbolAddress((void**)&p_h,   g_h);
    cudaGetSymbolAddress((void**)&p_qkv, g_qkv);
    cudaGetSymbolAddress((void**)&p_att, g_att);
    cudaGetSymbolAddress((void**)&p_out, g_out);

    norm_kernel<<<32, 1024>>>(x);
    gemm_bias<<<dim3(256 / 128, M_ / 128), 256>>>(p_xn,  W_proj, b_proj, p_h,   M_, 256, 32);
    gemm_bias<<<dim3(768 / 128, M_ / 128), 256>>>(p_h,   W_qkv,  b_qkv,  p_qkv, M_, 768, 256);
    attn_kernel<<<dim3(16, 32), 256, ATT_SMEM>>>();
    gemm_bias<<<dim3(256 / 128, M_ / 128), 256>>>(p_att, W_out,  b_out,  p_out, M_, 256, 256);
    head_loss_kernel<<<M_ / 32, 256, HEAD_SMEM>>>(W_head, b_head);
    finalize_kernel<<<1, 1>>>(out);
}

// round 3
// speedup vs baseline: 1.0853x; 1.0853x over previous
#include <cuda_runtime.h>
#include <math.h>

#define B_  32
#define L_  32768
#define PS_ 32
#define D_  256
#define T_  1024
#define M_  (B_ * T_)          // 32768 total patch rows

#define NEG_INF __int_as_float(0xff800000)

// ---------------- scratch (module-static device memory; no runtime alloc) ---
__device__ float  g_xn [B_ * L_];          //  4 MB  normalized x (== patches)
__device__ float  g_h  [M_ * D_];          // 32 MB  patch embeddings
__device__ float  g_qkv[M_ * 3 * D_];      // 96 MB  q|k|v
__device__ float  g_att[M_ * D_];          // 32 MB  attention output
__device__ float  g_out[M_ * D_];          // 32 MB  out-proj
__device__ double g_loss;

// ============================================================================
// 1) Instance norm over full series, ddof=1, std + 1e-5 (torch semantics)
// ============================================================================
__global__ void norm_kernel(const float* __restrict__ x) {
    const int b   = blockIdx.x;
    const int tid = threadIdx.x;            // 1024 threads
    const float* xr = x + (size_t)b * L_;

    float s = 0.f, ss = 0.f;
    for (int i = tid; i < L_; i += 1024) {
        float v = xr[i];
        s += v; ss += v * v;
    }
    __shared__ float sh_s[1024], sh_ss[1024];
    sh_s[tid] = s; sh_ss[tid] = ss;
    __syncthreads();
    for (int o = 512; o > 0; o >>= 1) {
        if (tid < o) { sh_s[tid] += sh_s[tid + o]; sh_ss[tid] += sh_ss[tid + o]; }
        __syncthreads();
    }
    const float sum  = sh_s[0];
    const float mean = sum / (float)L_;
    const float var  = (sh_ss[0] - sum * mean) / (float)(L_ - 1);   // ddof=1
    const float inv  = 1.0f / (sqrtf(var) + 1e-5f);

    float* o = g_xn + (size_t)b * L_;
    for (int i = tid; i < L_; i += 1024) o[i] = (xr[i] - mean) * inv;

    if (b == 0 && tid == 0) g_loss = 0.0;   // stream-ordered before head kernel
}

// ============================================================================
// 2) Tiled SGEMM: C[M][N] = A[M][K] @ W[K][N] + bias
//    BM=BN=128, BK=16, 256 threads, 8x8 register tiles (2x2 quadrants of 4x4).
// ============================================================================
__global__ void __launch_bounds__(256) gemm_bias(
    const float* __restrict__ A, const float* __restrict__ W,
    const float* __restrict__ bias, float* __restrict__ C,
    int M, int N, int K)
{
    __shared__ float Ast[16][132];   // transposed: Ast[k][m], padded
    __shared__ float Bs [16][128];

    const int tid = threadIdx.x;
    const int tx  = tid & 15, ty = tid >> 4;          // 16x16 thread grid
    const int m0  = blockIdx.y * 128, n0 = blockIdx.x * 128;

    const int a_row0 = tid >> 2,          a_c4 = tid & 3;
    const int a_row1 = (tid + 256) >> 2;
    const int b_row0 = tid >> 5,          b_c4 = tid & 31;
    const int b_row1 = (tid + 256) >> 5;

    float acc[8][8];
    #pragma unroll
    for (int i = 0; i < 8; i++)
        #pragma unroll
        for (int j = 0; j < 8; j++) acc[i][j] = 0.f;

    for (int kk = 0; kk < K; kk += 16) {
        float4 a0 = *(const float4*)(A + (size_t)(m0 + a_row0) * K + kk + a_c4 * 4);
        float4 a1 = *(const float4*)(A + (size_t)(m0 + a_row1) * K + kk + a_c4 * 4);
        float4 w0 = *(const float4*)(W + (size_t)(kk + b_row0) * N + n0 + b_c4 * 4);
        float4 w1 = *(const float4*)(W + (size_t)(kk + b_row1) * N + n0 + b_c4 * 4);

        Ast[a_c4 * 4 + 0][a_row0] = a0.x;
        Ast[a_c4 * 4 + 1][a_row0] = a0.y;
        Ast[a_c4 * 4 + 2][a_row0] = a0.z;
        Ast[a_c4 * 4 + 3][a_row0] = a0.w;
        Ast[a_c4 * 4 + 0][a_row1] = a1.x;
        Ast[a_c4 * 4 + 1][a_row1] = a1.y;
        Ast[a_c4 * 4 + 2][a_row1] = a1.z;
        Ast[a_c4 * 4 + 3][a_row1] = a1.w;
        *(float4*)&Bs[b_row0][b_c4 * 4] = w0;
        *(float4*)&Bs[b_row1][b_c4 * 4] = w1;
        __syncthreads();

        #pragma unroll
        for (int k = 0; k < 16; k++) {
            float4 va0 = *(const float4*)&Ast[k][ty * 4];
            float4 va1 = *(const float4*)&Ast[k][64 + ty * 4];
            float4 vb0 = *(const float4*)&Bs [k][tx * 4];
            float4 vb1 = *(const float4*)&Bs [k][64 + tx * 4];
            float af[8] = {va0.x, va0.y, va0.z, va0.w, va1.x, va1.y, va1.z, va1.w};
            float bf[8] = {vb0.x, vb0.y, vb0.z, vb0.w, vb1.x, vb1.y, vb1.z, vb1.w};
            #pragma unroll
            for (int i = 0; i < 8; i++)
                #pragma unroll
                for (int j = 0; j < 8; j++)
                    acc[i][j] = fmaf(af[i], bf[j], acc[i][j]);
        }
        __syncthreads();
    }

    const float4 bia0 = *(const float4*)(bias + n0 + tx * 4);
    const float4 bia1 = *(const float4*)(bias + n0 + 64 + tx * 4);
    #pragma unroll
    for (int i = 0; i < 8; i++) {
        const int row = m0 + ((i < 4) ? (ty * 4 + i) : (64 + ty * 4 + i - 4));
        float* cp = C + (size_t)row * N + n0;
        float4 o0, o1;
        o0.x = acc[i][0] + bia0.x; o0.y = acc[i][1] + bia0.y;
        o0.z = acc[i][2] + bia0.z; o0.w = acc[i][3] + bia0.w;
        o1.x = acc[i][4] + bia1.x; o1.y = acc[i][5] + bia1.y;
        o1.z = acc[i][6] + bia1.z; o1.w = acc[i][7] + bia1.w;
        *(float4*)(cp + tx * 4)      = o0;
        *(float4*)(cp + 64 + tx * 4) = o1;
    }
}

// ============================================================================
// 3) Causal flash attention, BQ=BK=64, D=256, fp32.
//    Qt/Kt padded to stride 68 (16B-aligned rows) with lane-over-row transpose
//    stores -> conflict-free STS (the R2 profile showed 32-way conflicts here:
//    L1=66.6% vs fma=16.5%). Global K/Q reads become row-scattered (accepted:
//    DRAM/L2 were at 1-1.5%).
// ============================================================================
#define KT_STRIDE 68
#define ATT_SMEM_FLOATS (2 * 256 * KT_STRIDE + 64 * 256 + 64 * 65 + 192)

__global__ void __launch_bounds__(256, 1) attn_kernel() {
    extern __shared__ float sm[];
    float* Qt      = sm;                          // [256][68] (scaled by 1/16)
    float* Kt      = sm + 256 * KT_STRIDE;        // [256][68]
    float* Vs      = sm + 2 * 256 * KT_STRIDE;    // [64][256]
    float* S       = Vs + 64 * 256;               // [64][65]
    float* m_row   = S + 64 * 65;
    float* l_row   = m_row + 64;
    float* alpha_s = l_row + 64;

    const int tid = threadIdx.x;
    const int b   = blockIdx.y;
    const int qb  = 15 - (int)blockIdx.x;   // heavy q-blocks first
    const int t0  = qb * 64;
    const int ty  = tid >> 4, tx = tid & 15;

    // Load Q^T, pre-scaled by 1/16. Lanes vary over row r -> conflict-free STS.
    {
        const float* qbase = g_qkv + (size_t)(b * T_ + t0) * 768;
        for (int fi = tid; fi < 64 * 64; fi += 256) {
            int dv = fi >> 6, r = fi & 63;           // lane-consecutive r
            float4 v = *(const float4*)(qbase + (size_t)r * 768 + dv * 4);
            Qt[(dv * 4 + 0) * KT_STRIDE + r] = v.x * 0.0625f;
            Qt[(dv * 4 + 1) * KT_STRIDE + r] = v.y * 0.0625f;
            Qt[(dv * 4 + 2) * KT_STRIDE + r] = v.z * 0.0625f;
            Qt[(dv * 4 + 3) * KT_STRIDE + r] = v.w * 0.0625f;
        }
    }
    if (tid < 64) { m_row[tid] = NEG_INF; l_row[tid] = 0.f; }

    float4 o4[4][4];
    #pragma unroll
    for (int i = 0; i < 4; i++)
        #pragma unroll
        for (int j = 0; j < 4; j++) o4[i][j] = make_float4(0.f, 0.f, 0.f, 0.f);

    for (int kb = 0; kb <= qb; kb++) {
        __syncthreads();   // protects Kt/Vs reuse; covers Q-load + stats init on iter 0

        // ---- load K^T (lane-over-row, conflict-free STS) and V (coalesced) ----
        {
            const float* kvb = g_qkv + (size_t)(b * T_ + kb * 64) * 768;
            for (int fi = tid; fi < 64 * 64; fi += 256) {
                int dv = fi >> 6, r = fi & 63;
                float4 kv = *(const float4*)(kvb + (size_t)r * 768 + 256 + dv * 4);
                Kt[(dv * 4 + 0) * KT_STRIDE + r] = kv.x;
                Kt[(dv * 4 + 1) * KT_STRIDE + r] = kv.y;
                Kt[(dv * 4 + 2) * KT_STRIDE + r] = kv.z;
                Kt[(dv * 4 + 3) * KT_STRIDE + r] = kv.w;
            }
            for (int fi = tid; fi < 64 * 64; fi += 256) {
                int r = fi >> 6, dv = fi & 63;
                float4 vv = *(const float4*)(kvb + (size_t)r * 768 + 512 + dv * 4);
                *(float4*)(Vs + r * 256 + dv * 4) = vv;
            }
        }
        __syncthreads();

        // ---- Phase A: S = (Q*scale) @ K^T, 4x4 register tile per thread ----
        float acc[4][4];
        #pragma unroll
        for (int i = 0; i < 4; i++)
            #pragma unroll
            for (int j = 0; j < 4; j++) acc[i][j] = 0.f;

        #pragma unroll 4
        for (int d = 0; d < 256; d++) {
            float4 qa = *(const float4*)(Qt + d * KT_STRIDE + ty * 4);
            float4 ka = *(const float4*)(Kt + d * KT_STRIDE + tx * 4);
            float qv[4] = {qa.x, qa.y, qa.z, qa.w};
            float kv[4] = {ka.x, ka.y, ka.z, ka.w};
            #pragma unroll
            for (int i = 0; i < 4; i++)
                #pragma unroll
                for (int j = 0; j < 4; j++)
                    acc[i][j] = fmaf(qv[i], kv[j], acc[i][j]);
        }
        const bool diag = (kb == qb);
        #pragma unroll
        for (int i = 0; i < 4; i++)
            #pragma unroll
            for (int j = 0; j < 4; j++) {
                float v = acc[i][j];
                if (diag && (tx * 4 + j > ty * 4 + i)) v = NEG_INF;
                S[(ty * 4 + i) * 65 + tx * 4 + j] = v;
            }
        __syncthreads();

        // ---- Phase B: online softmax (4 lanes per row) ----
        {
            const int row = tid >> 2, qq = tid & 3;
            float sv[16];
            float mloc = NEG_INF;
            #pragma unroll
            for (int j = 0; j < 16; j++) {
                sv[j] = S[row * 65 + qq * 16 + j];
                mloc  = fmaxf(mloc, sv[j]);
            }
            mloc = fmaxf(mloc, __shfl_xor_sync(0xffffffffu, mloc, 1));
            mloc = fmaxf(mloc, __shfl_xor_sync(0xffffffffu, mloc, 2));
            const float m_prev = m_row[row];
            const float m_new  = fmaxf(m_prev, mloc);
            const float al     = __expf(m_prev - m_new);   // exp(-inf)=0 on iter 0
            float lloc = 0.f;
            #pragma unroll
            for (int j = 0; j < 16; j++) {
                float p = __expf(sv[j] - m_new);           // masked -inf -> 0
                S[row * 65 + qq * 16 + j] = p;
                lloc += p;
            }
            lloc += __shfl_xor_sync(0xffffffffu, lloc, 1);
            lloc += __shfl_xor_sync(0xffffffffu, lloc, 2);
            if (qq == 0) {
                l_row[row]   = l_row[row] * al + lloc;
                m_row[row]   = m_new;
                alpha_s[row] = al;
            }
        }
        __syncthreads();

        // ---- Phase C: O = O*alpha + P @ V ----
        {
            #pragma unroll
            for (int i = 0; i < 4; i++) {
                float a = alpha_s[ty * 4 + i];
                #pragma unroll
                for (int j = 0; j < 4; j++) {
                    o4[i][j].x *= a; o4[i][j].y *= a;
                    o4[i][j].z *= a; o4[i][j].w *= a;
                }
            }
            #pragma unroll 2
            for (int k = 0; k < 64; k++) {
                float p[4];
                #pragma unroll
                for (int i = 0; i < 4; i++) p[i] = S[(ty * 4 + i) * 65 + k];
                float4 vv[4];
                #pragma unroll
                for (int j = 0; j < 4; j++)
                    vv[j] = *(const float4*)(Vs + k * 256 + tx * 16 + j * 4);
                #pragma unroll
                for (int i = 0; i < 4; i++)
                    #pragma unroll
                    for (int j = 0; j < 4; j++) {
                        o4[i][j].x = fmaf(p[i], vv[j].x, o4[i][j].x);
                        o4[i][j].y = fmaf(p[i], vv[j].y, o4[i][j].y);
                        o4[i][j].z = fmaf(p[i], vv[j].z, o4[i][j].z);
                        o4[i][j].w = fmaf(p[i], vv[j].w, o4[i][j].w);
                    }
            }
        }
    }

    // ---- epilogue: normalize by l, write out (coalesced float4) ----
    #pragma unroll
    for (int i = 0; i < 4; i++) {
        const float inv = 1.0f / l_row[ty * 4 + i];
        float* ob = g_att + (size_t)(b * T_ + t0 + ty * 4 + i) * 256 + tx * 16;
        #pragma unroll
        for (int j = 0; j < 4; j++) {
            float4 v = o4[i][j];
            v.x *= inv; v.y *= inv; v.z *= inv; v.w *= inv;
            *(float4*)(ob + j * 4) = v;
        }
    }
}

// ============================================================================
// 4) Head GEMM (K=256, N=32) fused with shifted-target MSE reduction
// ============================================================================
#define HEAD_SMEM_FLOATS (8192 + 32 * 260 + 256)

__global__ void __launch_bounds__(256) head_loss_kernel(
    const float* __restrict__ Wh, const float* __restrict__ bh)
{
    extern __shared__ float hsm[];
    float* Whs = hsm;                // [256][32]
    float* As  = hsm + 8192;         // [32][260] padded
    float* red = As + 32 * 260;      // [256]

    const int tid = threadIdx.x;
    const int m0  = blockIdx.x * 32;

    for (int fi = tid; fi < 2048; fi += 256)
        *(float4*)(Whs + fi * 4) = *(const float4*)(Wh + fi * 4);
    for (int fi = tid; fi < 2048; fi += 256) {
        int r = fi >> 6, dv = fi & 63;
        *(float4*)(As + r * 260 + dv * 4) =
            *(const float4*)(g_out + (size_t)(m0 + r) * 256 + dv * 4);
    }
    __syncthreads();

    const int rl = tid >> 3, cq = tid & 7;
    float a0 = 0.f, a1 = 0.f, a2 = 0.f, a3 = 0.f;
    #pragma unroll 8
    for (int k = 0; k < 256; k++) {
        float  a = As[rl * 260 + k];
        float4 w = *(const float4*)(Whs + k * 32 + cq * 4);
        a0 = fmaf(a, w.x, a0); a1 = fmaf(a, w.y, a1);
        a2 = fmaf(a, w.z, a2); a3 = fmaf(a, w.w, a3);
    }

    const int m = m0 + rl;
    const int t = m & 1023;
    const int bb = m >> 10;
    float part = 0.f;
    if (t < 1023) {   // pred[:, :-1] vs patches[:, 1:]
        const float* tg = g_xn + (size_t)bb * L_ + (t + 1) * 32 + cq * 4;
        float4 b4 = *(const float4*)(bh + cq * 4);
        float d0 = a0 + b4.x - tg[0];
        float d1 = a1 + b4.y - tg[1];
        float d2 = a2 + b4.z - tg[2];
        float d3 = a3 + b4.w - tg[3];
        part = d0 * d0 + d1 * d1 + d2 * d2 + d3 * d3;
    }
    red[tid] = part;
    __syncthreads();
    for (int o = 128; o > 0; o >>= 1) {
        if (tid < o) red[tid] += red[tid + o];
        __syncthreads();
    }
    if (tid == 0) atomicAdd(&g_loss, (double)red[0]);
}

__global__ void finalize_kernel(float* __restrict__ out) {
    out[0] = (float)(g_loss * (1.0 / (32.0 * 1023.0 * 32.0)));
}

// ============================================================================
// launch
// ============================================================================
extern "C" void kernel_launch(void* const* d_in, const int* in_sizes, int n_in,
                              void* d_out, int out_size) {
    (void)in_sizes; (void)n_in; (void)out_size;
    const float* x      = (const float*)d_in[0];
    const float* W_proj = (const float*)d_in[1];
    const float* b_proj = (const float*)d_in[2];
    const float* W_qkv  = (const float*)d_in[3];
    const float* b_qkv  = (const float*)d_in[4];
    const float* W_out  = (const float*)d_in[5];
    const float* b_out  = (const float*)d_in[6];
    const float* W_head = (const float*)d_in[7];
    const float* b_head = (const float*)d_in[8];
    float* out = (float*)d_out;

    const int ATT_SMEM  = ATT_SMEM_FLOATS  * 4;   // 222208 B
    const int HEAD_SMEM = HEAD_SMEM_FLOATS * 4;   //  67072 B
    cudaFuncSetAttribute(attn_kernel,
        cudaFuncAttributeMaxDynamicSharedMemorySize, ATT_SMEM);
    cudaFuncSetAttribute(head_loss_kernel,
        cudaFuncAttributeMaxDynamicSharedMemorySize, HEAD_SMEM);

    float *p_xn, *p_h, *p_qkv, *p_att, *p_out;
    cudaGetSymbolAddress((void**)&p_xn,  g_xn);
    cudaGetSymbolAddress((void**)&p_h,   g_h);
    cudaGetSymbolAddress((void**)&p_qkv, g_qkv);
    cudaGetSymbolAddress((void**)&p_att, g_att);
    cudaGetSymbolAddress((void**)&p_out, g_out);

    norm_kernel<<<32, 1024>>>(x);
    gemm_bias<<<dim3(256 / 128, M_ / 128), 256>>>(p_xn,  W_proj, b_proj, p_h,   M_, 256, 32);
    gemm_bias<<<dim3(768 / 128, M_ / 128), 256>>>(p_h,   W_qkv,  b_qkv,  p_qkv, M_, 768, 256);
    attn_kernel<<<dim3(16, 32), 256, ATT_SMEM>>>();
    gemm_bias<<<dim3(256 / 128, M_ / 128), 256>>>(p_att, W_out,  b_out,  p_out, M_, 256, 256);
    head_loss_kernel<<<M_ / 32, 256, HEAD_SMEM>>>(W_head, b_head);
    finalize_kernel<<<1, 1>>>(out);
}

// round 4
// speedup vs baseline: 1.0887x; 1.0032x over previous
#include <cuda_runtime.h>
#include <math.h>

#define B_  32
#define L_  32768
#define PS_ 32
#define D_  256
#define T_  1024
#define M_  (B_ * T_)          // 32768 total patch rows

#define NEG_INF __int_as_float(0xff800000)

// ---------------- scratch (module-static device memory; no runtime alloc) ---
__device__ float  g_xn [B_ * L_];          //  4 MB  normalized x (== patches)
__device__ float  g_h  [M_ * D_];          // 32 MB  patch embeddings
__device__ float  g_qkv[M_ * 3 * D_];      // 96 MB  q|k|v
__device__ float  g_att[M_ * D_];          // 32 MB  attention output
__device__ float  g_out[M_ * D_];          // 32 MB  out-proj
__device__ double g_loss;

// ============================================================================
// 1) Instance norm over full series, ddof=1, std + 1e-5 (torch semantics)
// ============================================================================
__global__ void norm_kernel(const float* __restrict__ x) {
    const int b   = blockIdx.x;
    const int tid = threadIdx.x;            // 1024 threads
    const float* xr = x + (size_t)b * L_;

    float s = 0.f, ss = 0.f;
    for (int i = tid; i < L_; i += 1024) {
        float v = xr[i];
        s += v; ss += v * v;
    }
    __shared__ float sh_s[1024], sh_ss[1024];
    sh_s[tid] = s; sh_ss[tid] = ss;
    __syncthreads();
    for (int o = 512; o > 0; o >>= 1) {
        if (tid < o) { sh_s[tid] += sh_s[tid + o]; sh_ss[tid] += sh_ss[tid + o]; }
        __syncthreads();
    }
    const float sum  = sh_s[0];
    const float mean = sum / (float)L_;
    const float var  = (sh_ss[0] - sum * mean) / (float)(L_ - 1);   // ddof=1
    const float inv  = 1.0f / (sqrtf(var) + 1e-5f);

    float* o = g_xn + (size_t)b * L_;
    for (int i = tid; i < L_; i += 1024) o[i] = (xr[i] - mean) * inv;

    if (b == 0 && tid == 0) g_loss = 0.0;   // stream-ordered before head kernel
}

// ============================================================================
// 2) Tiled SGEMM: C[M][N] = A[M][K] @ W[K][N] + bias
//    BM=BN=128, BK=16, 256 threads, 8x8 register tiles (2x2 quadrants of 4x4).
// ============================================================================
__global__ void __launch_bounds__(256) gemm_bias(
    const float* __restrict__ A, const float* __restrict__ W,
    const float* __restrict__ bias, float* __restrict__ C,
    int M, int N, int K)
{
    __shared__ float Ast[16][132];   // transposed: Ast[k][m], padded
    __shared__ float Bs [16][128];

    const int tid = threadIdx.x;
    const int tx  = tid & 15, ty = tid >> 4;          // 16x16 thread grid
    const int m0  = blockIdx.y * 128, n0 = blockIdx.x * 128;

    const int a_row0 = tid >> 2,          a_c4 = tid & 3;
    const int a_row1 = (tid + 256) >> 2;
    const int b_row0 = tid >> 5,          b_c4 = tid & 31;
    const int b_row1 = (tid + 256) >> 5;

    float acc[8][8];
    #pragma unroll
    for (int i = 0; i < 8; i++)
        #pragma unroll
        for (int j = 0; j < 8; j++) acc[i][j] = 0.f;

    for (int kk = 0; kk < K; kk += 16) {
        float4 a0 = *(const float4*)(A + (size_t)(m0 + a_row0) * K + kk + a_c4 * 4);
        float4 a1 = *(const float4*)(A + (size_t)(m0 + a_row1) * K + kk + a_c4 * 4);
        float4 w0 = *(const float4*)(W + (size_t)(kk + b_row0) * N + n0 + b_c4 * 4);
        float4 w1 = *(const float4*)(W + (size_t)(kk + b_row1) * N + n0 + b_c4 * 4);

        Ast[a_c4 * 4 + 0][a_row0] = a0.x;
        Ast[a_c4 * 4 + 1][a_row0] = a0.y;
        Ast[a_c4 * 4 + 2][a_row0] = a0.z;
        Ast[a_c4 * 4 + 3][a_row0] = a0.w;
        Ast[a_c4 * 4 + 0][a_row1] = a1.x;
        Ast[a_c4 * 4 + 1][a_row1] = a1.y;
        Ast[a_c4 * 4 + 2][a_row1] = a1.z;
        Ast[a_c4 * 4 + 3][a_row1] = a1.w;
        *(float4*)&Bs[b_row0][b_c4 * 4] = w0;
        *(float4*)&Bs[b_row1][b_c4 * 4] = w1;
        __syncthreads();

        #pragma unroll
        for (int k = 0; k < 16; k++) {
            float4 va0 = *(const float4*)&Ast[k][ty * 4];
            float4 va1 = *(const float4*)&Ast[k][64 + ty * 4];
            float4 vb0 = *(const float4*)&Bs [k][tx * 4];
            float4 vb1 = *(const float4*)&Bs [k][64 + tx * 4];
            float af[8] = {va0.x, va0.y, va0.z, va0.w, va1.x, va1.y, va1.z, va1.w};
            float bf[8] = {vb0.x, vb0.y, vb0.z, vb0.w, vb1.x, vb1.y, vb1.z, vb1.w};
            #pragma unroll
            for (int i = 0; i < 8; i++)
                #pragma unroll
                for (int j = 0; j < 8; j++)
                    acc[i][j] = fmaf(af[i], bf[j], acc[i][j]);
        }
        __syncthreads();
    }

    const float4 bia0 = *(const float4*)(bias + n0 + tx * 4);
    const float4 bia1 = *(const float4*)(bias + n0 + 64 + tx * 4);
    #pragma unroll
    for (int i = 0; i < 8; i++) {
        const int row = m0 + ((i < 4) ? (ty * 4 + i) : (64 + ty * 4 + i - 4));
        float* cp = C + (size_t)row * N + n0;
        float4 o0, o1;
        o0.x = acc[i][0] + bia0.x; o0.y = acc[i][1] + bia0.y;
        o0.z = acc[i][2] + bia0.z; o0.w = acc[i][3] + bia0.w;
        o1.x = acc[i][4] + bia1.x; o1.y = acc[i][5] + bia1.y;
        o1.z = acc[i][6] + bia1.z; o1.w = acc[i][7] + bia1.w;
        *(float4*)(cp + tx * 4)      = o0;
        *(float4*)(cp + 64 + tx * 4) = o1;
    }
}

// ============================================================================
// 3) Causal flash attention, BQ=BK=64, D=256, fp32.
//    Qt/Kt padded to stride 68 (16B-aligned rows) with lane-over-row transpose
//    stores -> conflict-free STS (the R2 profile showed 32-way conflicts here:
//    L1=66.6% vs fma=16.5%). Global K/Q reads become row-scattered (accepted:
//    DRAM/L2 were at 1-1.5%).
// ============================================================================
#define KT_STRIDE 68
#define ATT_SMEM_FLOATS (2 * 256 * KT_STRIDE + 64 * 256 + 64 * 65 + 192)

__global__ void __launch_bounds__(256, 1) attn_kernel() {
    extern __shared__ float sm[];
    float* Qt      = sm;                          // [256][68] (scaled by 1/16)
    float* Kt      = sm + 256 * KT_STRIDE;        // [256][68]
    float* Vs      = sm + 2 * 256 * KT_STRIDE;    // [64][256]
    float* S       = Vs + 64 * 256;               // [64][65]
    float* m_row   = S + 64 * 65;
    float* l_row   = m_row + 64;
    float* alpha_s = l_row + 64;

    const int tid = threadIdx.x;
    const int b   = blockIdx.y;
    const int qb  = 15 - (int)blockIdx.x;   // heavy q-blocks first
    const int t0  = qb * 64;
    const int ty  = tid >> 4, tx = tid & 15;

    // Load Q^T, pre-scaled by 1/16. Lanes vary over row r -> conflict-free STS.
    {
        const float* qbase = g_qkv + (size_t)(b * T_ + t0) * 768;
        for (int fi = tid; fi < 64 * 64; fi += 256) {
            int dv = fi >> 6, r = fi & 63;           // lane-consecutive r
            float4 v = *(const float4*)(qbase + (size_t)r * 768 + dv * 4);
            Qt[(dv * 4 + 0) * KT_STRIDE + r] = v.x * 0.0625f;
            Qt[(dv * 4 + 1) * KT_STRIDE + r] = v.y * 0.0625f;
            Qt[(dv * 4 + 2) * KT_STRIDE + r] = v.z * 0.0625f;
            Qt[(dv * 4 + 3) * KT_STRIDE + r] = v.w * 0.0625f;
        }
    }
    if (tid < 64) { m_row[tid] = NEG_INF; l_row[tid] = 0.f; }

    float4 o4[4][4];
    #pragma unroll
    for (int i = 0; i < 4; i++)
        #pragma unroll
        for (int j = 0; j < 4; j++) o4[i][j] = make_float4(0.f, 0.f, 0.f, 0.f);

    for (int kb = 0; kb <= qb; kb++) {
        __syncthreads();   // protects Kt/Vs reuse; covers Q-load + stats init on iter 0

        // ---- load K^T (lane-over-row, conflict-free STS) and V (coalesced) ----
        {
            const float* kvb = g_qkv + (size_t)(b * T_ + kb * 64) * 768;
            for (int fi = tid; fi < 64 * 64; fi += 256) {
                int dv = fi >> 6, r = fi & 63;
                float4 kv = *(const float4*)(kvb + (size_t)r * 768 + 256 + dv * 4);
                Kt[(dv * 4 + 0) * KT_STRIDE + r] = kv.x;
                Kt[(dv * 4 + 1) * KT_STRIDE + r] = kv.y;
                Kt[(dv * 4 + 2) * KT_STRIDE + r] = kv.z;
                Kt[(dv * 4 + 3) * KT_STRIDE + r] = kv.w;
            }
            for (int fi = tid; fi < 64 * 64; fi += 256) {
                int r = fi >> 6, dv = fi & 63;
                float4 vv = *(const float4*)(kvb + (size_t)r * 768 + 512 + dv * 4);
                *(float4*)(Vs + r * 256 + dv * 4) = vv;
            }
        }
        __syncthreads();

        // ---- Phase A: S = (Q*scale) @ K^T, 4x4 register tile per thread ----
        float acc[4][4];
        #pragma unroll
        for (int i = 0; i < 4; i++)
            #pragma unroll
            for (int j = 0; j < 4; j++) acc[i][j] = 0.f;

        #pragma unroll 4
        for (int d = 0; d < 256; d++) {
            float4 qa = *(const float4*)(Qt + d * KT_STRIDE + ty * 4);
            float4 ka = *(const float4*)(Kt + d * KT_STRIDE + tx * 4);
            float qv[4] = {qa.x, qa.y, qa.z, qa.w};
            float kv[4] = {ka.x, ka.y, ka.z, ka.w};
            #pragma unroll
            for (int i = 0; i < 4; i++)
                #pragma unroll
                for (int j = 0; j < 4; j++)
                    acc[i][j] = fmaf(qv[i], kv[j], acc[i][j]);
        }
        const bool diag = (kb == qb);
        #pragma unroll
        for (int i = 0; i < 4; i++)
            #pragma unroll
            for (int j = 0; j < 4; j++) {
                float v = acc[i][j];
                if (diag && (tx * 4 + j > ty * 4 + i)) v = NEG_INF;
                S[(ty * 4 + i) * 65 + tx * 4 + j] = v;
            }
        __syncthreads();

        // ---- Phase B: online softmax (4 lanes per row) ----
        {
            const int row = tid >> 2, qq = tid & 3;
            float sv[16];
            float mloc = NEG_INF;
            #pragma unroll
            for (int j = 0; j < 16; j++) {
                sv[j] = S[row * 65 + qq * 16 + j];
                mloc  = fmaxf(mloc, sv[j]);
            }
            mloc = fmaxf(mloc, __shfl_xor_sync(0xffffffffu, mloc, 1));
            mloc = fmaxf(mloc, __shfl_xor_sync(0xffffffffu, mloc, 2));
            const float m_prev = m_row[row];
            const float m_new  = fmaxf(m_prev, mloc);
            const float al     = __expf(m_prev - m_new);   // exp(-inf)=0 on iter 0
            float lloc = 0.f;
            #pragma unroll
            for (int j = 0; j < 16; j++) {
                float p = __expf(sv[j] - m_new);           // masked -inf -> 0
                S[row * 65 + qq * 16 + j] = p;
                lloc += p;
            }
            lloc += __shfl_xor_sync(0xffffffffu, lloc, 1);
            lloc += __shfl_xor_sync(0xffffffffu, lloc, 2);
            if (qq == 0) {
                l_row[row]   = l_row[row] * al + lloc;
                m_row[row]   = m_new;
                alpha_s[row] = al;
            }
        }
        __syncthreads();

        // ---- Phase C: O = O*alpha + P @ V ----
        {
            #pragma unroll
            for (int i = 0; i < 4; i++) {
                float a = alpha_s[ty * 4 + i];
                #pragma unroll
                for (int j = 0; j < 4; j++) {
                    o4[i][j].x *= a; o4[i][j].y *= a;
                    o4[i][j].z *= a; o4[i][j].w *= a;
                }
            }
            #pragma unroll 2
            for (int k = 0; k < 64; k++) {
                float p[4];
                #pragma unroll
                for (int i = 0; i < 4; i++) p[i] = S[(ty * 4 + i) * 65 + k];
                float4 vv[4];
                #pragma unroll
                for (int j = 0; j < 4; j++)
                    vv[j] = *(const float4*)(Vs + k * 256 + tx * 16 + j * 4);
                #pragma unroll
                for (int i = 0; i < 4; i++)
                    #pragma unroll
                    for (int j = 0; j < 4; j++) {
                        o4[i][j].x = fmaf(p[i], vv[j].x, o4[i][j].x);
                        o4[i][j].y = fmaf(p[i], vv[j].y, o4[i][j].y);
                        o4[i][j].z = fmaf(p[i], vv[j].z, o4[i][j].z);
                        o4[i][j].w = fmaf(p[i], vv[j].w, o4[i][j].w);
                    }
            }
        }
    }

    // ---- epilogue: normalize by l, write out (coalesced float4) ----
    #pragma unroll
    for (int i = 0; i < 4; i++) {
        const float inv = 1.0f / l_row[ty * 4 + i];
        float* ob = g_att + (size_t)(b * T_ + t0 + ty * 4 + i) * 256 + tx * 16;
        #pragma unroll
        for (int j = 0; j < 4; j++) {
            float4 v = o4[i][j];
            v.x *= inv; v.y *= inv; v.z *= inv; v.w *= inv;
            *(float4*)(ob + j * 4) = v;
        }
    }
}

// ============================================================================
// 4) Head GEMM (K=256, N=32) fused with shifted-target MSE reduction
// ============================================================================
#define HEAD_SMEM_FLOATS (8192 + 32 * 260 + 256)

__global__ void __launch_bounds__(256) head_loss_kernel(
    const float* __restrict__ Wh, const float* __restrict__ bh)
{
    extern __shared__ float hsm[];
    float* Whs = hsm;                // [256][32]
    float* As  = hsm + 8192;         // [32][260] padded
    float* red = As + 32 * 260;      // [256]

    const int tid = threadIdx.x;
    const int m0  = blockIdx.x * 32;

    for (int fi = tid; fi < 2048; fi += 256)
        *(float4*)(Whs + fi * 4) = *(const float4*)(Wh + fi * 4);
    for (int fi = tid; fi < 2048; fi += 256) {
        int r = fi >> 6, dv = fi & 63;
        *(float4*)(As + r * 260 + dv * 4) =
            *(const float4*)(g_out + (size_t)(m0 + r) * 256 + dv * 4);
    }
    __syncthreads();

    const int rl = tid >> 3, cq = tid & 7;
    float a0 = 0.f, a1 = 0.f, a2 = 0.f, a3 = 0.f;
    #pragma unroll 8
    for (int k = 0; k < 256; k++) {
        float  a = As[rl * 260 + k];
        float4 w = *(const float4*)(Whs + k * 32 + cq * 4);
        a0 = fmaf(a, w.x, a0); a1 = fmaf(a, w.y, a1);
        a2 = fmaf(a, w.z, a2); a3 = fmaf(a, w.w, a3);
    }

    const int m = m0 + rl;
    const int t = m & 1023;
    const int bb = m >> 10;
    float part = 0.f;
    if (t < 1023) {   // pred[:, :-1] vs patches[:, 1:]
        const float* tg = g_xn + (size_t)bb * L_ + (t + 1) * 32 + cq * 4;
        float4 b4 = *(const float4*)(bh + cq * 4);
        float d0 = a0 + b4.x - tg[0];
        float d1 = a1 + b4.y - tg[1];
        float d2 = a2 + b4.z - tg[2];
        float d3 = a3 + b4.w - tg[3];
        part = d0 * d0 + d1 * d1 + d2 * d2 + d3 * d3;
    }
    red[tid] = part;
    __syncthreads();
    for (int o = 128; o > 0; o >>= 1) {
        if (tid < o) red[tid] += red[tid + o];
        __syncthreads();
    }
    if (tid == 0) atomicAdd(&g_loss, (double)red[0]);
}

__global__ void finalize_kernel(float* __restrict__ out) {
    out[0] = (float)(g_loss * (1.0 / (32.0 * 1023.0 * 32.0)));
}

// ============================================================================
// launch
// ============================================================================
extern "C" void kernel_launch(void* const* d_in, const int* in_sizes, int n_in,
                              void* d_out, int out_size) {
    (void)in_sizes; (void)n_in; (void)out_size;
    const float* x      = (const float*)d_in[0];
    const float* W_proj = (const float*)d_in[1];
    const float* b_proj = (const float*)d_in[2];
    const float* W_qkv  = (const float*)d_in[3];
    const float* b_qkv  = (const float*)d_in[4];
    const float* W_out  = (const float*)d_in[5];
    const float* b_out  = (const float*)d_in[6];
    const float* W_head = (const float*)d_in[7];
    const float* b_head = (const float*)d_in[8];
    float* out = (float*)d_out;

    const int ATT_SMEM  = ATT_SMEM_FLOATS  * 4;   // 222208 B
    const int HEAD_SMEM = HEAD_SMEM_FLOATS * 4;   //  67072 B
    cudaFuncSetAttribute(attn_kernel,
        cudaFuncAttributeMaxDynamicSharedMemorySize, ATT_SMEM);
    cudaFuncSetAttribute(head_loss_kernel,
        cudaFuncAttributeMaxDynamicSharedMemorySize, HEAD_SMEM);

    float *p_xn, *p_h, *p_qkv, *p_att, *p_out;
    cudaGetSymbolAddress((void**)&p_xn,  g_xn);
    cudaGetSymbolAddress((void**)&p_h,   g_h);
    cudaGetSymbolAddress((void**)&p_qkv, g_qkv);
    cudaGetSymbolAddress((void**)&p_att, g_att);
    cudaGetSymbolAddress((void**)&p_out, g_out);

    norm_kernel<<<32, 1024>>>(x);
    gemm_bias<<<dim3(256 / 128, M_ / 128), 256>>>(p_xn,  W_proj, b_proj, p_h,   M_, 256, 32);
    gemm_bias<<<dim3(768 / 128, M_ / 128), 256>>>(p_h,   W_qkv,  b_qkv,  p_qkv, M_, 768, 256);
    attn_kernel<<<dim3(16, 32), 256, ATT_SMEM>>>();
    gemm_bias<<<dim3(256 / 128, M_ / 128), 256>>>(p_att, W_out,  b_out,  p_out, M_, 256, 256);
    head_loss_kernel<<<M_ / 32, 256, HEAD_SMEM>>>(W_head, b_head);
    finalize_kernel<<<1, 1>>>(out);
}